// round 9
// baseline (speedup 1.0000x reference)
#include <cuda_runtime.h>

// BoxBlur 13x13 reflect, (8,64,512,512) fp32.
// Tall-stripe streaming: CTA = 128-row x 512-col stripe, processed as eight
// 16-row chunks with the vertical running sum carried across chunks
// (LDG/out 2.75 -> 2.09, halo re-reads 1.75x -> 1.09x).
// Per-chunk internals = round-3 winner: 8-wide ring pass 2, staged os,
// float4 coalesced flush.

#define Wd 512
#define Hd 512
#define TYC 16            // rows per chunk
#define NCH 8             // chunks per CTA -> 128 rows
#define NT 512
#define PW 513            // vs stride (conflict-free row-strided access)
#define OW 516            // os stride (float4-aligned)
#define KHALF 6

#define SMEM_FLOATS (TYC * PW + 8 * OW)
#define SMEM_BYTES  (SMEM_FLOATS * 4)       // 49,344 B -> 3 CTAs/SM

__device__ __forceinline__ int reflect_i(int i, int n) {
    // jnp.pad 'reflect', pad (6) < n: single fold.
    if (i < 0) i = -i;
    if (i >= n) i = 2 * n - 2 - i;
    return i;
}

__global__ __launch_bounds__(NT, 3)
void boxblur9(const float* __restrict__ in,
              const float* __restrict__ kern,
              float* __restrict__ out) {
    extern __shared__ float sm[];
    float* __restrict__ vs = sm;              // [TYC][PW] vertical 13-sums
    float* __restrict__ os = sm + TYC * PW;   // [8][OW]   output staging

    const int ybase = blockIdx.x * (TYC * NCH);
    const int plane = blockIdx.y;
    const float* __restrict__ ip = in  + (size_t)plane * (Hd * Wd);
    float*       __restrict__ op = out + (size_t)plane * (Hd * Wd);
    const int t = threadIdx.x;                // 0..511
    const float k0 = kern[0];                 // 1/169

    // pass-2 / flush lane maps (constant across chunks)
    const int rl  = t & 7;          // pass2: local row within half
    const int seg = t >> 3;         // pass2: 0..63, 8-wide x segment
    const int xb  = seg * 8;
    const int g   = t & 127;        // flush: float4 column group
    const int r2  = t >> 7;         // flush: row base (0..3)

    // ---- init vertical running sum once per CTA (12 rows) ----
    float s = 0.0f;
    #pragma unroll
    for (int j = -KHALF; j < KHALF; j++)
        s += ip[reflect_i(ybase + j, Hd) * Wd + t];

    #pragma unroll 1
    for (int c = 0; c < NCH; c++) {
        const int y0 = ybase + c * TYC;

        // ---- Pass 1: vertical running 13-sum for this chunk ----
        #pragma unroll
        for (int j = 0; j < TYC; j++) {
            s += ip[reflect_i(y0 + j + KHALF, Hd) * Wd + t];   // incoming
            vs[j * PW + t] = s;
            s -= ip[reflect_i(y0 + j - KHALF, Hd) * Wd + t];   // outgoing (cache hit)
        }
        __syncthreads();

        // ---- Pass 2: horizontal sliding 13-sums, two 8-row halves ----
        #pragma unroll
        for (int h = 0; h < 2; h++) {
            const int row = h * 8 + rl;
            const float* __restrict__ vrow = vs + row * PW;
            float ring[13];
            float hs = 0.0f;
            #pragma unroll
            for (int k = 0; k < 13; k++) {
                const float v = vrow[reflect_i(xb - KHALF + k, Wd)];
                ring[k] = v;
                hs += v;
            }
            #pragma unroll
            for (int i = 0; i < 8; i++) {
                os[rl * OW + xb + i] = hs * k0;
                const float v = vrow[reflect_i(xb + i + KHALF + 1, Wd)];
                hs += v - ring[i];
                ring[i] = v;
            }
            __syncthreads();
            // flush half chunk: float4 coalesced (LDS.128 + STG.128)
            #pragma unroll
            for (int rr = 0; rr < 2; rr++) {
                const int rowf = r2 + rr * 4;
                const float4 v4 = *(const float4*)&os[rowf * OW + 4 * g];
                *(float4*)&op[(size_t)(y0 + h * 8 + rowf) * Wd + 4 * g] = v4;
            }
            __syncthreads();   // also protects vs WAR for next chunk's pass 1
        }
    }
}

extern "C" void kernel_launch(void* const* d_in, const int* in_sizes, int n_in,
                              void* d_out, int out_size) {
    const float* input  = (const float*)d_in[0];   // (8,64,512,512) fp32
    const float* kernel = (const float*)d_in[1];   // (1,13,13) fp32 uniform
    float* out = (float*)d_out;

    cudaFuncSetAttribute(boxblur9, cudaFuncAttributeMaxDynamicSharedMemorySize,
                         SMEM_BYTES);

    dim3 grid(Hd / (TYC * NCH), 8 * 64);    // (4 stripes, 512 planes)
    boxblur9<<<grid, NT, SMEM_BYTES>>>(input, kernel, out);
}

// round 10
// speedup vs baseline: 1.3846x; 1.3846x over previous
#include <cuda_runtime.h>

// BoxBlur 13x13 reflect, (8,64,512,512) fp32. Separable, sliding-window.
// = round-3 winner (192us) with ONE change: os stride 516 -> 513, making the
//   pass-2 staging STS conflict-free (was 4-way: banks (4rl+8seg+i)%32 hit
//   only 8 banks). Flush becomes scalar with lane map x = g + 128e
//   (conflict-free LDS, fully coalesced STG; same wavefronts as float4 path).

#define Wd 512
#define Hd 512
#define TY 16
#define NT 512
#define PW 513            // vs stride (conflict-free row-strided access)
#define OW 513            // os stride (conflict-free STS: (rl+8seg+i)%32 covers all banks)
#define KHALF 6

#define SMEM_FLOATS (TY * PW + 8 * OW)
#define SMEM_BYTES  (SMEM_FLOATS * 4)       // 49,248 B -> 3 CTAs/SM

__device__ __forceinline__ int reflect_i(int i, int n) {
    // jnp.pad 'reflect', pad (6) < n: single fold.
    if (i < 0) i = -i;
    if (i >= n) i = 2 * n - 2 - i;
    return i;
}

__global__ __launch_bounds__(NT, 3)
void boxblur10(const float* __restrict__ in,
               const float* __restrict__ kern,
               float* __restrict__ out) {
    extern __shared__ float sm[];
    float* __restrict__ vs = sm;             // [TY][PW]  vertical 13-sums
    float* __restrict__ os = sm + TY * PW;   // [8][OW]   output staging

    const int ytile = blockIdx.x;
    const int plane = blockIdx.y;
    const int y0 = ytile * TY;
    const float* __restrict__ ip = in  + (size_t)plane * (Hd * Wd);
    float*       __restrict__ op = out + (size_t)plane * (Hd * Wd);
    const int t = threadIdx.x;               // 0..511
    const float k0 = kern[0];                // 1/169

    // ---- Pass 1: vertical running 13-sum, thread t = column t ----
    // (reload form: outgoing-row re-read hits L1/L2; register ring spills
    //  at this occupancy — R6/R7 post-mortems)
    {
        float s = 0.0f;
        #pragma unroll
        for (int j = -KHALF; j < KHALF; j++)           // 12 init rows
            s += ip[reflect_i(y0 + j, Hd) * Wd + t];
        #pragma unroll
        for (int j = 0; j < TY; j++) {
            s += ip[reflect_i(y0 + j + KHALF, Hd) * Wd + t];   // incoming
            vs[j * PW + t] = s;
            s -= ip[reflect_i(y0 + j - KHALF, Hd) * Wd + t];   // outgoing (cache hit)
        }
    }
    __syncthreads();

    // ---- Pass 2: horizontal sliding 13-sums, two 8-row halves ----
    const int rl  = t & 7;          // local row within half
    const int seg = t >> 3;         // 0..63, 8-wide x segment
    const int xb  = seg * 8;
    const int g   = t & 127;        // flush: column lane
    const int r2  = t >> 7;         // flush: row base (0..3)

    #pragma unroll
    for (int h = 0; h < 2; h++) {
        const int row = h * 8 + rl;
        const float* __restrict__ vrow = vs + row * PW;
        float ring[13];
        float s = 0.0f;
        #pragma unroll
        for (int k = 0; k < 13; k++) {
            const float v = vrow[reflect_i(xb - KHALF + k, Wd)];
            ring[k] = v;
            s += v;
        }
        #pragma unroll
        for (int i = 0; i < 8; i++) {
            os[rl * OW + xb + i] = s * k0;          // STS, conflict-free now
            const float v = vrow[reflect_i(xb + i + KHALF + 1, Wd)];
            s += v - ring[i];
            ring[i] = v;
        }
        __syncthreads();
        // flush half tile: scalar, lane map x = g + 128e
        // LDS banks = g%32 (conflict-free); STG lanes consecutive (coalesced)
        #pragma unroll
        for (int rr = 0; rr < 2; rr++) {
            const int rowf = r2 + rr * 4;
            float* __restrict__ od = op + (size_t)(y0 + h * 8 + rowf) * Wd;
            const float* __restrict__ osr = os + rowf * OW;
            #pragma unroll
            for (int e = 0; e < 4; e++) {
                od[g + 128 * e] = osr[g + 128 * e];
            }
        }
        __syncthreads();
    }
}

extern "C" void kernel_launch(void* const* d_in, const int* in_sizes, int n_in,
                              void* d_out, int out_size) {
    const float* input  = (const float*)d_in[0];   // (8,64,512,512) fp32
    const float* kernel = (const float*)d_in[1];   // (1,13,13) fp32 uniform
    float* out = (float*)d_out;

    cudaFuncSetAttribute(boxblur10, cudaFuncAttributeMaxDynamicSharedMemorySize,
                         SMEM_BYTES);

    dim3 grid(Hd / TY, 8 * 64);    // (32 y-tiles, 512 planes)
    boxblur10<<<grid, NT, SMEM_BYTES>>>(input, kernel, out);
}